// round 3
// baseline (speedup 1.0000x reference)
#include <cuda_runtime.h>
#include <math.h>
#include <stdint.h>

// ---------------- problem constants ----------------
#define Dm   1024
#define Hh   16
#define HD   64
#define DFF  4096
#define Sv   5
#define Bb   2048
#define Ll   6
#define NSEQ (6*2048)          // 12288
#define NROW (NSEQ*Ll)         // 73728
#define NQ   20480             // selected query rows
#define OUTN ((size_t)6*2048*6*1024)

// ---------------- scratch (static device, no allocs) ----------------
__device__ float g_src   [(size_t)NROW*Dm];      // 302MB
__device__ float g_kv    [(size_t)NROW*2048];    // 604MB  (k | v per row)
__device__ float g_qsrc  [(size_t)NQ*Dm];
__device__ float g_q     [(size_t)NQ*Dm];
__device__ float g_ctx   [(size_t)NQ*Dm];
__device__ float g_msg   [(size_t)NQ*Dm];
__device__ float g_a1in  [(size_t)Bb*5120];
__device__ float g_a2in  [(size_t)Bb*5120];
__device__ float g_aggv  [(size_t)Bb*Dm];
__device__ float g_nagg  [(size_t)Bb*Dm];
__device__ float g_h1    [(size_t)Bb*5*Dm];
__device__ float g_r1    [(size_t)Bb*5*DFF];
__device__ float g_f1    [(size_t)Bb*5*Dm];
__device__ float g_s1    [(size_t)Bb*Dm];
__device__ float g_r2    [(size_t)Bb*DFF];
__device__ float g_f2    [(size_t)Bb*Dm];

// ---------------- src materialization ----------------
__global__ void k_src(const float* __restrict__ F, const float* __restrict__ R,
                      float* __restrict__ src) {
    long i4 = (long)blockIdx.x * blockDim.x + threadIdx.x;   // float4 index
    long r  = i4 >> 8;
    int  d4 = (int)(i4 & 255);
    int  l  = (int)(r % 6);
    long sb = r / 6;
    const float4* F4 = (const float4*)F;
    float4 v = F4[i4];
    if (l > 0) {
        const float4* R4 = (const float4*)R;
        float4 e = R4[(sb*5 + (l-1))*256 + d4];
        v.x += e.x; v.y += e.y; v.z += e.z; v.w += e.w;
    }
    ((float4*)src)[i4] = v;
}

// ---------------- gather selected query rows ----------------
__global__ void k_gatherq(const float* __restrict__ src, float* __restrict__ qsrc) {
    long i4 = (long)blockIdx.x * blockDim.x + threadIdx.x;
    int i  = (int)(i4 >> 8);
    int d4 = (int)(i4 & 255);
    long rs;
    if (i < 10240) { int sp = i / 2048, b = i % 2048; rs = ((long)(sp+1)*2048 + b)*6; }
    else           { int j = i - 10240; int m = j / 2048, b = j % 2048; rs = (long)b*6 + m + 1; }
    ((float4*)qsrc)[i4] = ((const float4*)src)[rs*256 + d4];
}

// ---------------- tf32 tensor-core GEMM ----------------
// C[M,N] = A[M,K] @ W[N,K]^T + bias, epilogue. All dims: M%128==0, N%128==0, K%32==0.
// 256 threads = 8 warps in 2x4; warp tile 64x32 via m16n8k8 tf32 mma (4x4 tiles).
__device__ __forceinline__ uint32_t f2tf32(float x) {
    uint32_t r;
    asm("cvt.rna.tf32.f32 %0, %1;" : "=r"(r) : "f"(x));
    return r;
}

template<int EPI>   // 0=none, 1=relu, 2=sigmoid
__global__ void __launch_bounds__(256) mma_nt(
    int M, int N, int K,
    const float* __restrict__ A, const float* __restrict__ W,
    const float* __restrict__ bias, float* __restrict__ C)
{
    __shared__ float As[128][36];
    __shared__ float Bs[128][36];
    const int tid  = threadIdx.x;
    const int warp = tid >> 5, lane = tid & 31;
    const int wm = warp >> 2, wn = warp & 3;          // 2 x 4 warps
    const long bm = (long)blockIdx.y * 128;
    const long bn = (long)blockIdx.x * 128;

    const int srow = tid >> 3;          // 0..31 (row within 32-row pass)
    const int scol = (tid & 7) * 4;     // 0..28

    float acc[4][4][4];
    #pragma unroll
    for (int i = 0; i < 4; i++)
        #pragma unroll
        for (int j = 0; j < 4; j++)
            #pragma unroll
            for (int r = 0; r < 4; r++) acc[i][j][r] = 0.f;

    float4 ra[4], rb[4];
    const float* Abase = A + (bm + srow) * K + scol;
    const float* Wbase = W + (bn + srow) * K + scol;

    #pragma unroll
    for (int p = 0; p < 4; p++) {
        ra[p] = *(const float4*)(Abase + (long)p*32*K);
        rb[p] = *(const float4*)(Wbase + (long)p*32*K);
    }

    const int gr = lane >> 2;      // 0..7
    const int tg = lane & 3;       // 0..3

    for (int k0 = 0; k0 < K; k0 += 32) {
        __syncthreads();
        #pragma unroll
        for (int p = 0; p < 4; p++) {
            int rr = p*32 + srow;
            As[rr][scol+0] = __uint_as_float(f2tf32(ra[p].x));
            As[rr][scol+1] = __uint_as_float(f2tf32(ra[p].y));
            As[rr][scol+2] = __uint_as_float(f2tf32(ra[p].z));
            As[rr][scol+3] = __uint_as_float(f2tf32(ra[p].w));
            Bs[rr][scol+0] = __uint_as_float(f2tf32(rb[p].x));
            Bs[rr][scol+1] = __uint_as_float(f2tf32(rb[p].y));
            Bs[rr][scol+2] = __uint_as_float(f2tf32(rb[p].z));
            Bs[rr][scol+3] = __uint_as_float(f2tf32(rb[p].w));
        }
        __syncthreads();

        if (k0 + 32 < K) {
            #pragma unroll
            for (int p = 0; p < 4; p++) {
                ra[p] = *(const float4*)(Abase + (long)p*32*K + k0 + 32);
                rb[p] = *(const float4*)(Wbase + (long)p*32*K + k0 + 32);
            }
        }

        #pragma unroll
        for (int ks = 0; ks < 4; ks++) {
            const int kb = ks * 8;
            uint32_t af[4][4], bf[4][2];
            #pragma unroll
            for (int mt = 0; mt < 4; mt++) {
                int r0 = wm*64 + mt*16 + gr;
                af[mt][0] = __float_as_uint(As[r0    ][kb + tg    ]);
                af[mt][1] = __float_as_uint(As[r0 + 8][kb + tg    ]);
                af[mt][2] = __float_as_uint(As[r0    ][kb + tg + 4]);
                af[mt][3] = __float_as_uint(As[r0 + 8][kb + tg + 4]);
            }
            #pragma unroll
            for (int nt = 0; nt < 4; nt++) {
                int n0 = wn*32 + nt*8 + gr;
                bf[nt][0] = __float_as_uint(Bs[n0][kb + tg    ]);
                bf[nt][1] = __float_as_uint(Bs[n0][kb + tg + 4]);
            }
            #pragma unroll
            for (int mt = 0; mt < 4; mt++)
                #pragma unroll
                for (int nt = 0; nt < 4; nt++) {
                    asm volatile(
                        "mma.sync.aligned.m16n8k8.row.col.f32.tf32.tf32.f32 "
                        "{%0,%1,%2,%3}, {%4,%5,%6,%7}, {%8,%9}, {%0,%1,%2,%3};"
                        : "+f"(acc[mt][nt][0]), "+f"(acc[mt][nt][1]),
                          "+f"(acc[mt][nt][2]), "+f"(acc[mt][nt][3])
                        : "r"(af[mt][0]), "r"(af[mt][1]), "r"(af[mt][2]), "r"(af[mt][3]),
                          "r"(bf[nt][0]), "r"(bf[nt][1]));
                }
        }
    }

    // epilogue
    #pragma unroll
    for (int mt = 0; mt < 4; mt++) {
        long row0 = bm + wm*64 + mt*16 + gr;
        #pragma unroll
        for (int nt = 0; nt < 4; nt++) {
            int col0 = (int)bn + wn*32 + nt*8 + tg*2;
            float bv0 = __ldg(bias + col0);
            float bv1 = __ldg(bias + col0 + 1);
            float v00 = acc[mt][nt][0] + bv0;
            float v01 = acc[mt][nt][1] + bv1;
            float v10 = acc[mt][nt][2] + bv0;
            float v11 = acc[mt][nt][3] + bv1;
            if (EPI == 1) {
                v00 = fmaxf(v00, 0.f); v01 = fmaxf(v01, 0.f);
                v10 = fmaxf(v10, 0.f); v11 = fmaxf(v11, 0.f);
            }
            if (EPI == 2) {
                v00 = 1.f/(1.f+expf(-v00)); v01 = 1.f/(1.f+expf(-v01));
                v10 = 1.f/(1.f+expf(-v10)); v11 = 1.f/(1.f+expf(-v11));
            }
            *(float2*)(C + row0*N + col0)       = make_float2(v00, v01);
            *(float2*)(C + (row0+8)*N + col0)   = make_float2(v10, v11);
        }
    }
}

// ---------------- attention (L=6, warp per (q-row, head)) ----------------
__global__ void k_attn(const float* __restrict__ q, const float* __restrict__ kv,
                       float* __restrict__ ctx) {
    int i = blockIdx.x;
    int seq;
    if (i < 10240) { int sp = i / 2048, b = i % 2048; seq = (sp+1)*2048 + b; }
    else           { seq = (i - 10240) % 2048; }
    const int warp = threadIdx.x >> 5, lane = threadIdx.x & 31;
    const float* kvbase = kv + (long)seq * 6 * 2048;
    for (int h = warp; h < 16; h += 8) {
        const float* qp = q + (long)i*1024 + h*64;
        float q0 = qp[lane*2], q1 = qp[lane*2+1];
        float sc[6];
        #pragma unroll
        for (int j = 0; j < 6; j++) {
            const float* kp = kvbase + j*2048 + h*64;
            float p = q0*kp[lane*2] + q1*kp[lane*2+1];
            #pragma unroll
            for (int o = 16; o; o >>= 1) p += __shfl_xor_sync(0xffffffffu, p, o);
            sc[j] = p * 0.125f;
        }
        float mx = sc[0];
        #pragma unroll
        for (int j = 1; j < 6; j++) mx = fmaxf(mx, sc[j]);
        float sum = 0.f;
        #pragma unroll
        for (int j = 0; j < 6; j++) { sc[j] = expf(sc[j]-mx); sum += sc[j]; }
        float inv = 1.f / sum;
        float o0 = 0.f, o1 = 0.f;
        #pragma unroll
        for (int j = 0; j < 6; j++) {
            const float* vp = kvbase + j*2048 + 1024 + h*64;
            float wgt = sc[j]*inv;
            o0 = fmaf(wgt, vp[lane*2],   o0);
            o1 = fmaf(wgt, vp[lane*2+1], o1);
        }
        float* op = ctx + (long)i*1024 + h*64;
        op[lane*2] = o0; op[lane*2+1] = o1;
    }
}

// ---------------- scatter msg rows into agg GEMM layouts ----------------
__global__ void k_scatter(const float* __restrict__ msg,
                          float* __restrict__ a1, float* __restrict__ a2) {
    long i4 = (long)blockIdx.x * blockDim.x + threadIdx.x;
    int i  = (int)(i4 >> 8);
    int d4 = (int)(i4 & 255);
    float4 v = ((const float4*)msg)[i4];
    if (i < 10240) { int sp = i/2048, b = i%2048; ((float4*)a1)[(long)b*1280 + sp*256 + d4] = v; }
    else { int j = i-10240; int m = j/2048, b = j%2048; ((float4*)a2)[(long)b*1280 + m*256 + d4] = v; }
}

// ---------------- LayerNorm helpers ----------------
__device__ __forceinline__ float block_sum256(float v) {
    __shared__ float sh[9];
    int lane = threadIdx.x & 31, w = threadIdx.x >> 5;
    #pragma unroll
    for (int o = 16; o; o >>= 1) v += __shfl_xor_sync(0xffffffffu, v, o);
    if (lane == 0) sh[w] = v;
    __syncthreads();
    if (w == 0) {
        float r = (lane < 8) ? sh[lane] : 0.f;
        #pragma unroll
        for (int o = 4; o; o >>= 1) r += __shfl_xor_sync(0xffffffffu, r, o);
        if (lane == 0) sh[8] = r;
    }
    __syncthreads();
    float out = sh[8];
    __syncthreads();
    return out;
}

__device__ __forceinline__ void ln_row(const float* pa, const float* pb,
                                       const float* g, const float* bvec, float* po) {
    int tid = threadIdx.x;
    float v[4];
    #pragma unroll
    for (int t = 0; t < 4; t++) v[t] = pa[tid + t*256] + pb[tid + t*256];
    float mu = block_sum256(v[0]+v[1]+v[2]+v[3]) * (1.f/1024.f);
    float qv = 0.f;
    #pragma unroll
    for (int t = 0; t < 4; t++) { float d = v[t]-mu; qv += d*d; }
    float var = block_sum256(qv) * (1.f/1024.f);
    float r = rsqrtf(var + 1e-5f);
    #pragma unroll
    for (int t = 0; t < 4; t++) {
        int idx = tid + t*256;
        po[idx] = (v[t]-mu)*r*g[idx] + bvec[idx];
    }
}

__global__ void k_ln1(const float* __restrict__ F, const float* __restrict__ aggv,
                      const float* __restrict__ g, const float* __restrict__ bv,
                      float* __restrict__ out) {
    int row = blockIdx.x; int b = row/5, m = row%5;
    ln_row(F + ((long)b*6 + 1 + m)*1024, aggv + (long)b*1024, g, bv, out + (long)row*1024);
}
__global__ void k_ln2(const float* __restrict__ h1, const float* __restrict__ f1,
                      const float* __restrict__ g, const float* __restrict__ bv,
                      float* __restrict__ out) {
    int row = blockIdx.x; int b = row/5, m = row%5;
    ln_row(h1 + (long)row*1024, f1 + (long)row*1024, g, bv, out + ((long)b*6 + 1 + m)*1024);
}
__global__ void k_ln3(const float* __restrict__ F, const float* __restrict__ nagg,
                      const float* __restrict__ g, const float* __restrict__ bv,
                      float* __restrict__ out) {
    int b = blockIdx.x;
    ln_row(F + (long)b*6*1024, nagg + (long)b*1024, g, bv, out + (long)b*1024);
}
__global__ void k_ln4(const float* __restrict__ s1, const float* __restrict__ f2,
                      const float* __restrict__ g, const float* __restrict__ bv,
                      float* __restrict__ out) {
    int b = blockIdx.x;
    ln_row(s1 + (long)b*1024, f2 + (long)b*1024, g, bv, out + (long)b*6*1024);
}

// ---------------- host ----------------
static float* symaddr(const void* sym) {
    void* p = nullptr;
    cudaGetSymbolAddress(&p, sym);
    return (float*)p;
}

extern "C" void kernel_launch(void* const* d_in, const int* in_sizes, int n_in,
                              void* d_out, int out_size) {
    (void)in_sizes; (void)n_in; (void)out_size;
    const float* F     = (const float*)d_in[0];
    const float* R     = (const float*)d_in[1];
    const float* w_in  = (const float*)d_in[2];
    const float* b_in  = (const float*)d_in[3];
    const float* w_out = (const float*)d_in[4];
    const float* b_out = (const float*)d_in[5];
    const float* ln1g  = (const float*)d_in[6];
    const float* ln1b  = (const float*)d_in[7];
    const float* ln2g  = (const float*)d_in[8];
    const float* ln2b  = (const float*)d_in[9];
    const float* ln3g  = (const float*)d_in[10];
    const float* ln3b  = (const float*)d_in[11];
    const float* ln4g  = (const float*)d_in[12];
    const float* ln4b  = (const float*)d_in[13];
    const float* f1w1  = (const float*)d_in[14];
    const float* f1b1  = (const float*)d_in[15];
    const float* f1w2  = (const float*)d_in[16];
    const float* f1b2  = (const float*)d_in[17];
    const float* f2w1  = (const float*)d_in[18];
    const float* f2b1  = (const float*)d_in[19];
    const float* f2w2  = (const float*)d_in[20];
    const float* f2b2  = (const float*)d_in[21];
    const float* a1w   = (const float*)d_in[22];
    const float* a1b   = (const float*)d_in[23];
    const float* a2w   = (const float*)d_in[24];
    const float* a2b   = (const float*)d_in[25];
    float* out = (float*)d_out;

    float* src   = symaddr(g_src);
    float* kv    = symaddr(g_kv);
    float* qsrc  = symaddr(g_qsrc);
    float* q     = symaddr(g_q);
    float* ctx   = symaddr(g_ctx);
    float* msg   = symaddr(g_msg);
    float* a1in  = symaddr(g_a1in);
    float* a2in  = symaddr(g_a2in);
    float* aggv  = symaddr(g_aggv);
    float* nagg  = symaddr(g_nagg);
    float* h1    = symaddr(g_h1);
    float* r1    = symaddr(g_r1);
    float* f1    = symaddr(g_f1);
    float* s1    = symaddr(g_s1);
    float* r2    = symaddr(g_r2);
    float* f2    = symaddr(g_f2);

    // passthrough copy of the whole features tensor (slice 0 overwritten later)
    cudaMemcpyAsync(out, F, OUTN * sizeof(float), cudaMemcpyDeviceToDevice, 0);

    // src = verb | noun + role
    k_src<<<NROW, 256>>>(F, R, src);
    k_gatherq<<<NQ, 256>>>(src, qsrc);

    // KV for all rows
    mma_nt<0><<<dim3(2048/128, NROW/128), 256>>>(NROW, 2048, 1024,
        src, w_in + (size_t)1024*1024, b_in + 1024, kv);
    // Q for selected rows
    mma_nt<0><<<dim3(1024/128, NQ/128), 256>>>(NQ, 1024, 1024,
        qsrc, w_in, b_in, q);

    k_attn<<<NQ, 256>>>(q, kv, ctx);

    // out projection
    mma_nt<0><<<dim3(1024/128, NQ/128), 256>>>(NQ, 1024, 1024,
        ctx, w_out, b_out, msg);
    k_scatter<<<NQ, 256>>>(msg, a1in, a2in);

    // aggregation gates
    mma_nt<2><<<dim3(1024/128, Bb/128), 256>>>(Bb, 1024, 5120, a1in, a1w, a1b, aggv);
    mma_nt<2><<<dim3(1024/128, Bb/128), 256>>>(Bb, 1024, 5120, a2in, a2w, a2b, nagg);

    // noun path
    k_ln1<<<Bb*5, 256>>>(F, aggv, ln1g, ln1b, h1);
    mma_nt<1><<<dim3(DFF/128, (Bb*5)/128), 256>>>(Bb*5, DFF, 1024, h1, f1w1, f1b1, r1);
    mma_nt<0><<<dim3(1024/128, (Bb*5)/128), 256>>>(Bb*5, 1024, DFF, r1, f1w2, f1b2, f1);
    k_ln2<<<Bb*5, 256>>>(h1, f1, ln2g, ln2b, out);

    // verb path
    k_ln3<<<Bb, 256>>>(F, nagg, ln3g, ln3b, s1);
    mma_nt<1><<<dim3(DFF/128, Bb/128), 256>>>(Bb, DFF, 1024, s1, f2w1, f2b1, r2);
    mma_nt<0><<<dim3(1024/128, Bb/128), 256>>>(Bb, 1024, DFF, r2, f2w2, f2b2, f2);
    k_ln4<<<Bb, 256>>>(s1, f2, ln4g, ln4b, out);
}

// round 6
// speedup vs baseline: 1.6933x; 1.6933x over previous
#include <cuda_runtime.h>
#include <cuda_fp16.h>
#include <math.h>
#include <stdint.h>

#define Dm 1024
#define DFF 4096
#define Bb 2048
#define NROW 73728
#define NQ 20480
#define OUTN ((size_t)6*2048*6*1024)

// ---------------- scratch ----------------
__device__ __half g_srch [(size_t)NROW*Dm];
__device__ __half g_kvh  [(size_t)NROW*2048];
__device__ __half g_qsrch[(size_t)NQ*Dm];
__device__ __half g_qh   [(size_t)NQ*Dm];
__device__ __half g_ctxh [(size_t)NQ*Dm];
__device__ __half g_msgh [(size_t)NQ*Dm];
__device__ __half g_a1inh[(size_t)Bb*5120];
__device__ __half g_a2inh[(size_t)Bb*5120];
__device__ float  g_aggv [(size_t)Bb*Dm];
__device__ float  g_nagg [(size_t)Bb*Dm];
__device__ float  g_h1   [(size_t)Bb*5*Dm];
__device__ __half g_h1h  [(size_t)Bb*5*Dm];
__device__ __half g_r1h  [(size_t)Bb*5*DFF];
__device__ float  g_f1   [(size_t)Bb*5*Dm];
__device__ float  g_s1   [(size_t)Bb*Dm];
__device__ __half g_s1h  [(size_t)Bb*Dm];
__device__ __half g_r2h  [(size_t)Bb*DFF];
__device__ float  g_f2   [(size_t)Bb*Dm];
__device__ __half g_wh   [(size_t)31457280];
#define WIN  0
#define WOUT 3145728
#define A1W  4194304
#define A2W  9437184
#define F1W1 14680064
#define F1W2 18874368
#define F2W1 23068672
#define F2W2 27262976

__device__ __forceinline__ uint32_t smem_u32(const void* p) {
    uint32_t a;
    asm("{ .reg .u64 t; cvta.to.shared.u64 t, %1; cvt.u32.u64 %0, t; }" : "=r"(a) : "l"(p));
    return a;
}
__device__ __forceinline__ void cp16(uint32_t dst, const __half* src) {
    asm volatile("cp.async.cg.shared.global [%0], [%1], 16;"
                 :: "r"(dst), "l"(__cvta_generic_to_global(src)) : "memory");
}
#define CP_COMMIT() asm volatile("cp.async.commit_group;" ::: "memory")
#define CP_WAIT(n)  asm volatile("cp.async.wait_group %0;" :: "n"(n) : "memory")

// ---------------- f16 mma.sync GEMM: C[M,N]=A[M,K]@W[N,K]^T+bias ----------------
// 128x128 tile, BK=32, 256 thr, warp 64x32 (m16n8k16 x 4x4), cp.async double-buffer.
// smem rows padded to 80B (40 halves): ldmatrix bank-conflict-free.
template<int EPI, int OUT16>   // EPI: 0 none, 1 relu, 2 sigmoid
__global__ void __launch_bounds__(256, 2) hgemm(
    int M, int N, int K,
    const __half* __restrict__ A, const __half* __restrict__ W,
    const float* __restrict__ bias, void* __restrict__ Cv)
{
    __shared__ __half As[2][128*40];
    __shared__ __half Bs[2][128*40];
    const uint32_t sa = smem_u32(As), sbm = smem_u32(Bs);
    const int tid = threadIdx.x;
    const int warp = tid >> 5, lane = tid & 31;
    const int wm = warp >> 2, wn = warp & 3;
    const long bm = (long)blockIdx.y * 128;
    const long bn = (long)blockIdx.x * 128;
    const int gr = lane >> 2, tg = lane & 3;

    float acc[4][4][4];
    #pragma unroll
    for (int i = 0; i < 4; i++)
        #pragma unroll
        for (int j = 0; j < 4; j++) {
            acc[i][j][0] = 0.f; acc[i][j][1] = 0.f;
            acc[i][j][2] = 0.f; acc[i][j][3] = 0.f;
        }

    const int S = K >> 5;
    auto stage = [&](int s, int b) {
        const int k0 = s << 5;
        #pragma unroll
        for (int i = 0; i < 2; i++) {
            int ch = tid + (i << 8);          // 0..511
            int r = ch >> 2, c = ch & 3;
            cp16(sa  + (uint32_t)(b*10240 + r*80 + c*16), A + (bm + r)*(long)K + k0 + c*8);
            cp16(sbm + (uint32_t)(b*10240 + r*80 + c*16), W + (bn + r)*(long)K + k0 + c*8);
        }
    };

    stage(0, 0); CP_COMMIT();

    for (int s = 0; s < S; s++) {
        const int buf = s & 1;
        if (s + 1 < S) { stage(s + 1, buf ^ 1); CP_COMMIT(); CP_WAIT(1); }
        else           { CP_WAIT(0); }
        __syncthreads();

        #pragma unroll
        for (int ks = 0; ks < 2; ks++) {
            uint32_t af[4][4], bf[4][2];
            #pragma unroll
            for (int mt = 0; mt < 4; mt++) {
                int row = wm*64 + mt*16 + (lane & 15);
                uint32_t p = sa + (uint32_t)(buf*10240 + row*80 + (ks*2 + (lane >> 4))*16);
                asm volatile("ldmatrix.sync.aligned.m8n8.x4.shared.b16 {%0,%1,%2,%3}, [%4];"
                    : "=r"(af[mt][0]), "=r"(af[mt][1]), "=r"(af[mt][2]), "=r"(af[mt][3])
                    : "r"(p));
            }
            #pragma unroll
            for (int nt = 0; nt < 4; nt++) {
                int rown = wn*32 + nt*8 + (lane & 7);
                uint32_t p = sbm + (uint32_t)(buf*10240 + rown*80 + (ks*2 + ((lane >> 3) & 1))*16);
                asm volatile("ldmatrix.sync.aligned.m8n8.x2.shared.b16 {%0,%1}, [%2];"
                    : "=r"(bf[nt][0]), "=r"(bf[nt][1]) : "r"(p));
            }
            #pragma unroll
            for (int mt = 0; mt < 4; mt++)
                #pragma unroll
                for (int nt = 0; nt < 4; nt++) {
                    asm volatile(
                        "mma.sync.aligned.m16n8k16.row.col.f32.f16.f16.f32 "
                        "{%0,%1,%2,%3}, {%4,%5,%6,%7}, {%8,%9}, {%0,%1,%2,%3};"
                        : "+f"(acc[mt][nt][0]), "+f"(acc[mt][nt][1]),
                          "+f"(acc[mt][nt][2]), "+f"(acc[mt][nt][3])
                        : "r"(af[mt][0]), "r"(af[mt][1]), "r"(af[mt][2]), "r"(af[mt][3]),
                          "r"(bf[nt][0]), "r"(bf[nt][1]));
                }
        }
        __syncthreads();
    }

    // epilogue
    #pragma unroll
    for (int mt = 0; mt < 4; mt++) {
        long row0 = bm + wm*64 + mt*16 + gr;
        #pragma unroll
        for (int nt = 0; nt < 4; nt++) {
            int col0 = (int)bn + wn*32 + nt*8 + tg*2;
            float bv0 = __ldg(bias + col0);
            float bv1 = __ldg(bias + col0 + 1);
            float v00 = acc[mt][nt][0] + bv0;
            float v01 = acc[mt][nt][1] + bv1;
            float v10 = acc[mt][nt][2] + bv0;
            float v11 = acc[mt][nt][3] + bv1;
            if (EPI == 1) {
                v00 = fmaxf(v00, 0.f); v01 = fmaxf(v01, 0.f);
                v10 = fmaxf(v10, 0.f); v11 = fmaxf(v11, 0.f);
            }
            if (EPI == 2) {
                v00 = 1.f/(1.f+__expf(-v00)); v01 = 1.f/(1.f+__expf(-v01));
                v10 = 1.f/(1.f+__expf(-v10)); v11 = 1.f/(1.f+__expf(-v11));
            }
            if (OUT16) {
                __half* C = (__half*)Cv;
                *(__half2*)(C + row0*(long)N + col0)     = __floats2half2_rn(v00, v01);
                *(__half2*)(C + (row0+8)*(long)N + col0) = __floats2half2_rn(v10, v11);
            } else {
                float* C = (float*)Cv;
                *(float2*)(C + row0*(long)N + col0)     = make_float2(v00, v01);
                *(float2*)(C + (row0+8)*(long)N + col0) = make_float2(v10, v11);
            }
        }
    }
}

// ---------------- small kernels ----------------
__global__ void k_cvt(const float4* __restrict__ s, uint2* __restrict__ d, long n4) {
    long i = (long)blockIdx.x * blockDim.x + threadIdx.x;
    if (i >= n4) return;
    float4 v = s[i];
    __half2 a = __floats2half2_rn(v.x, v.y), b = __floats2half2_rn(v.z, v.w);
    d[i] = make_uint2(*(uint32_t*)&a, *(uint32_t*)&b);
}
__global__ void k_src(const float* __restrict__ F, const float* __restrict__ R,
                      __half* __restrict__ srch) {
    long i8 = (long)blockIdx.x * blockDim.x + threadIdx.x;
    long r = i8 >> 7; int d8 = (int)(i8 & 127);
    int l = (int)(r % 6); long sbq = r / 6;
    const float4* F4 = (const float4*)F;
    float4 v0 = F4[i8*2], v1 = F4[i8*2+1];
    if (l > 0) {
        const float4* R4 = (const float4*)R;
        long rb = (sbq*5 + (l-1))*256 + d8*2;
        float4 e0 = R4[rb], e1 = R4[rb+1];
        v0.x+=e0.x; v0.y+=e0.y; v0.z+=e0.z; v0.w+=e0.w;
        v1.x+=e1.x; v1.y+=e1.y; v1.z+=e1.z; v1.w+=e1.w;
    }
    __half2 h0=__floats2half2_rn(v0.x,v0.y), h1=__floats2half2_rn(v0.z,v0.w);
    __half2 h2=__floats2half2_rn(v1.x,v1.y), h3=__floats2half2_rn(v1.z,v1.w);
    ((uint4*)srch)[i8] = make_uint4(*(uint32_t*)&h0,*(uint32_t*)&h1,*(uint32_t*)&h2,*(uint32_t*)&h3);
}
__global__ void k_gatherq(const __half* __restrict__ s, __half* __restrict__ q) {
    long idx = (long)blockIdx.x * blockDim.x + threadIdx.x;
    int i = (int)(idx >> 7), d8 = (int)(idx & 127);
    long rs;
    if (i < 10240) { int sp = i/2048, b = i%2048; rs = ((long)(sp+1)*2048 + b)*6; }
    else           { int j = i-10240; int m = j/2048, b = j%2048; rs = (long)b*6 + m + 1; }
    ((uint4*)q)[idx] = ((const uint4*)s)[rs*128 + d8];
}
__global__ void k_attn(const __half* __restrict__ q, const __half* __restrict__ kv,
                       __half* __restrict__ ctx) {
    int i = blockIdx.x, seq;
    if (i < 10240) { int sp = i/2048, b = i%2048; seq = (sp+1)*2048 + b; }
    else           { seq = (i - 10240) % 2048; }
    const int warp = threadIdx.x >> 5, lane = threadIdx.x & 31;
    const __half* kb = kv + (long)seq * 12288;
    for (int h = warp; h < 16; h += 8) {
        float2 qf = __half22float2(*(const __half2*)(q + (long)i*1024 + h*64 + lane*2));
        float sc[6];
        #pragma unroll
        for (int j = 0; j < 6; j++) {
            float2 kf = __half22float2(*(const __half2*)(kb + j*2048 + h*64 + lane*2));
            float p = qf.x*kf.x + qf.y*kf.y;
            #pragma unroll
            for (int o = 16; o; o >>= 1) p += __shfl_xor_sync(0xffffffffu, p, o);
            sc[j] = p * 0.125f;
        }
        float mx = sc[0];
        #pragma unroll
        for (int j = 1; j < 6; j++) mx = fmaxf(mx, sc[j]);
        float sum = 0.f;
        #pragma unroll
        for (int j = 0; j < 6; j++) { sc[j] = __expf(sc[j]-mx); sum += sc[j]; }
        float inv = 1.f/sum, o0 = 0.f, o1 = 0.f;
        #pragma unroll
        for (int j = 0; j < 6; j++) {
            float2 vf = __half22float2(*(const __half2*)(kb + j*2048 + 1024 + h*64 + lane*2));
            o0 = fmaf(sc[j]*inv, vf.x, o0); o1 = fmaf(sc[j]*inv, vf.y, o1);
        }
        *(__half2*)(ctx + (long)i*1024 + h*64 + lane*2) = __floats2half2_rn(o0, o1);
    }
}
__global__ void k_scatter(const __half* __restrict__ msg,
                          __half* __restrict__ a1, __half* __restrict__ a2) {
    long idx = (long)blockIdx.x * blockDim.x + threadIdx.x;
    int i = (int)(idx >> 7), d8 = (int)(idx & 127);
    uint4 v = ((const uint4*)msg)[idx];
    if (i < 10240) { int sp = i/2048, b = i%2048; ((uint4*)a1)[(long)b*640 + sp*128 + d8] = v; }
    else { int j = i-10240; int m = j/2048, b = j%2048; ((uint4*)a2)[(long)b*640 + m*128 + d8] = v; }
}
__device__ __forceinline__ float bsum(float v) {
    __shared__ float sh[9];
    int lane = threadIdx.x & 31, w = threadIdx.x >> 5;
    #pragma unroll
    for (int o = 16; o; o >>= 1) v += __shfl_xor_sync(0xffffffffu, v, o);
    if (lane == 0) sh[w] = v;
    __syncthreads();
    if (w == 0) {
        float r = (lane < 8) ? sh[lane] : 0.f;
        #pragma unroll
        for (int o = 4; o; o >>= 1) r += __shfl_xor_sync(0xffffffffu, r, o);
        if (lane == 0) sh[8] = r;
    }
    __syncthreads();
    float out = sh[8];
    __syncthreads();
    return out;
}
__device__ __forceinline__ void ln_row(const float* pa, const float* pb,
                                       const float* g, const float* bv,
                                       float* po, __half* ph) {
    int tid = threadIdx.x;
    float v[4];
    #pragma unroll
    for (int t = 0; t < 4; t++) v[t] = pa[tid + t*256] + pb[tid + t*256];
    float mu = bsum(v[0]+v[1]+v[2]+v[3]) * (1.f/1024.f);
    float qv = 0.f;
    #pragma unroll
    for (int t = 0; t < 4; t++) { float d = v[t]-mu; qv += d*d; }
    float r = rsqrtf(bsum(qv) * (1.f/1024.f) + 1e-5f);
    #pragma unroll
    for (int t = 0; t < 4; t++) {
        int idx = tid + t*256;
        float o = (v[t]-mu)*r*g[idx] + bv[idx];
        po[idx] = o;
        if (ph) ph[idx] = __float2half_rn(o);
    }
}
__global__ void k_ln1(const float* F, const float* aggv, const float* g, const float* bv,
                      float* out, __half* outh) {
    int row = blockIdx.x; int b = row/5, m = row%5;
    ln_row(F + ((long)b*6+1+m)*1024, aggv + (long)b*1024, g, bv,
           out + (long)row*1024, outh + (long)row*1024);
}
__global__ void k_ln2(const float* h1, const float* f1, const float* g, const float* bv,
                      float* out) {
    int row = blockIdx.x; int b = row/5, m = row%5;
    ln_row(h1 + (long)row*1024, f1 + (long)row*1024, g, bv,
           out + ((long)b*6+1+m)*1024, (__half*)0);
}
__global__ void k_ln3(const float* F, const float* nagg, const float* g, const float* bv,
                      float* out, __half* outh) {
    int b = blockIdx.x;
    ln_row(F + (long)b*6144, nagg + (long)b*1024, g, bv,
           out + (long)b*1024, outh + (long)b*1024);
}
__global__ void k_ln4(const float* s1, const float* f2, const float* g, const float* bv,
                      float* out) {
    int b = blockIdx.x;
    ln_row(s1 + (long)b*1024, f2 + (long)b*1024, g, bv, out + (long)b*6144, (__half*)0);
}

// ---------------- host ----------------
template<typename T> static T* sym(const void* s) {
    void* p = nullptr; cudaGetSymbolAddress(&p, s); return (T*)p;
}
static void cvt(const float* s, __half* d, long n) {
    long n4 = n/4;
    k_cvt<<<(unsigned)((n4+255)/256), 256>>>((const float4*)s, (uint2*)d, n4);
}

extern "C" void kernel_launch(void* const* d_in, const int* in_sizes, int n_in,
                              void* d_out, int out_size) {
    (void)in_sizes; (void)n_in; (void)out_size;
    const float *F=(const float*)d_in[0], *R=(const float*)d_in[1];
    const float *w_in=(const float*)d_in[2], *b_in=(const float*)d_in[3];
    const float *w_out=(const float*)d_in[4], *b_out=(const float*)d_in[5];
    const float *ln1g=(const float*)d_in[6], *ln1b=(const float*)d_in[7];
    const float *ln2g=(const float*)d_in[8], *ln2b=(const float*)d_in[9];
    const float *ln3g=(const float*)d_in[10], *ln3b=(const float*)d_in[11];
    const float *ln4g=(const float*)d_in[12], *ln4b=(const float*)d_in[13];
    const float *f1w1=(const float*)d_in[14], *f1b1=(const float*)d_in[15];
    const float *f1w2=(const float*)d_in[16], *f1b2=(const float*)d_in[17];
    const float *f2w1=(const float*)d_in[18], *f2b1=(const float*)d_in[19];
    const float *f2w2=(const float*)d_in[20], *f2b2=(const float*)d_in[21];
    const float *a1w=(const float*)d_in[22], *a1b=(const float*)d_in[23];
    const float *a2w=(const float*)d_in[24], *a2b=(const float*)d_in[25];
    float* out = (float*)d_out;

    __half *srch=sym<__half>(g_srch), *kvh=sym<__half>(g_kvh);
    __half *qsrch=sym<__half>(g_qsrch), *qh=sym<__half>(g_qh);
    __half *ctxh=sym<__half>(g_ctxh), *msgh=sym<__half>(g_msgh);
    __half *a1inh=sym<__half>(g_a1inh), *a2inh=sym<__half>(g_a2inh);
    float *aggv=sym<float>(g_aggv), *nagg=sym<float>(g_nagg);
    float *h1=sym<float>(g_h1), *f1=sym<float>(g_f1);
    float *s1=sym<float>(g_s1), *f2=sym<float>(g_f2);
    __half *h1h=sym<__half>(g_h1h), *r1h=sym<__half>(g_r1h);
    __half *s1h=sym<__half>(g_s1h), *r2h=sym<__half>(g_r2h);
    __half *wh=sym<__half>(g_wh);

    cudaMemcpyAsync(out, F, OUTN*sizeof(float), cudaMemcpyDeviceToDevice, 0);

    cvt(w_in,  wh+WIN,  (long)3072*1024);
    cvt(w_out, wh+WOUT, (long)1024*1024);
    cvt(a1w,   wh+A1W,  (long)1024*5120);
    cvt(a2w,   wh+A2W,  (long)1024*5120);
    cvt(f1w1,  wh+F1W1, (long)4096*1024);
    cvt(f1w2,  wh+F1W2, (long)1024*4096);
    cvt(f2w1,  wh+F2W1, (long)4096*1024);
    cvt(f2w2,  wh+F2W2, (long)1024*4096);

    k_src<<<NROW/2, 256>>>(F, R, srch);
    k_gatherq<<<NQ/2, 256>>>(srch, qsrch);

    hgemm<0,1><<<dim3(16, NROW/128), 256>>>(NROW, 2048, 1024,
        srch, wh+WIN+(size_t)1024*1024, b_in+1024, kvh);
    hgemm<0,1><<<dim3(8, NQ/128), 256>>>(NQ, 1024, 1024, qsrch, wh+WIN, b_in, qh);

    k_attn<<<NQ, 256>>>(qh, kvh, ctxh);

    hgemm<0,1><<<dim3(8, NQ/128), 256>>>(NQ, 1024, 1024, ctxh, wh+WOUT, b_out, msgh);
    k_scatter<<<NQ/2, 256>>>(msgh, a1inh, a2inh);

    hgemm<2,0><<<dim3(8, Bb/128), 256>>>(Bb, 1024, 5120, a1inh, wh+A1W, a1b, aggv);
    hgemm<2,0><<<dim3(8, Bb/128), 256>>>(Bb, 1024, 5120, a2inh, wh+A2W, a2b, nagg);

    k_ln1<<<Bb*5, 256>>>(F, aggv, ln1g, ln1b, h1, h1h);
    hgemm<1,1><<<dim3(32, Bb*5/128), 256>>>(Bb*5, DFF, 1024, h1h, wh+F1W1, f1b1, r1h);
    hgemm<0,0><<<dim3(8, Bb*5/128), 256>>>(Bb*5, 1024, DFF, r1h, wh+F1W2, f1b2, f1);
    k_ln2<<<Bb*5, 256>>>(h1, f1, ln2g, ln2b, out);

    k_ln3<<<Bb, 256>>>(F, nagg, ln3g, ln3b, s1, s1h);
    hgemm<1,1><<<dim3(32, Bb/128), 256>>>(Bb, DFF, 1024, s1h, wh+F2W1, f2b1, r2h);
    hgemm<0,0><<<dim3(8, Bb/128), 256>>>(Bb, 1024, DFF, r2h, wh+F2W2, f2b2, f2);
    k_ln4<<<Bb, 256>>>(s1, f2, ln4g, ln4b, out);
}